// round 16
// baseline (speedup 1.0000x reference)
#include <cuda_runtime.h>
#include <math.h>

#define NPTS  8192
#define NBIN  256
#define TPB_B 256
#define TPB_S 256
#define QBLK  32                    // search blocks per dp
#define NBLK_S (QBLK*4)             // 128 search blocks
#define WPB   (TPB_S/32)            // 8 warps per block
#define QPW   (NPTS/(QBLK*WPB))     // 32 queries per warp

// Scratch (no allocs allowed)
__device__ float4       g_tmp[4][NPTS];      // unsorted transformed points
__device__ float4       g_db[4][NPTS];       // x-binned points (x,y,z,|p|^2)
__device__ int          g_bs[4][NBIN+1];     // bin start offsets (+sentinel)
__device__ float        g_xmin[4], g_inv[4];
__device__ double       g_bsum[NBLK_S];
__device__ unsigned int g_count;             // zero-init; tail resets -> replay-safe

__device__ __forceinline__ int bin_of(float x, float xmin, float inv) {
    int b = (int)((x - xmin) * inv);
    return min(NBIN - 1, max(0, b));
}
__device__ __forceinline__ float warp_min(float v) {
    #pragma unroll
    for (int o = 16; o; o >>= 1) v = fminf(v, __shfl_xor_sync(0xffffffffu, v, o));
    return v;
}
// per-lane min of (|p|^2 - 2 q.p) over db[s..e), lanes strided
__device__ __forceinline__ float scan_range(const float4* __restrict__ db, int s, int e,
                                            float nqx, float nqy, float nqz, int lane) {
    float m = 1e30f;
    for (int i = s + lane; i < e; i += 32) {
        float4 p = db[i];
        m = fminf(m, fmaf(nqx, p.x, fmaf(nqy, p.y, fmaf(nqz, p.z, p.w))));
    }
    return m;
}

// ---------------------------------------------------------------------------
// k_build: one block per dp (= dir + 2*part). Computes the transformed db set
// (dir0: cam raw; dir1: (B or T)@cad), finds x range, histograms into NBIN
// bins, scatters into g_db (counting sort; within-bin order irrelevant for
// min). dp0's thread 0 also writes the transform outputs.
// ---------------------------------------------------------------------------
__global__ void k_build(const float* __restrict__ cam, const float* __restrict__ cad,
                        const float* __restrict__ xyz, const float* __restrict__ rpy,
                        const float* __restrict__ quat, const float* __restrict__ bt,
                        const float* __restrict__ theta, float* __restrict__ out)
{
    __shared__ float sxf[12];
    __shared__ float sred[TPB_B];
    __shared__ int   shist[NBIN], sstart[NBIN + 1], soff[NBIN];
    __shared__ float s_xmin, s_inv;

    const int dp = blockIdx.x, part = dp >> 1, dir = dp & 1;
    const int tid = threadIdx.x;

    if (tid == 0) {
        float qa = quat[0], qb = quat[1], qc = quat[2], qd = quat[3];
        float qn = sqrtf(qa*qa + qb*qb + qc*qc + qd*qd);
        qa /= qn; qb /= qn; qc /= qn; qd /= qn;

        float B[16];
        B[0]  = 1.f - 2.f*qc*qc - 2.f*qd*qd;  B[1]  = 2.f*qb*qc - 2.f*qa*qd;        B[2]  = 2.f*qa*qc + 2.f*qb*qd;        B[3]  = bt[0];
        B[4]  = 2.f*qb*qc + 2.f*qa*qd;        B[5]  = 1.f - 2.f*qb*qb - 2.f*qd*qd;  B[6]  = 2.f*qc*qd - 2.f*qa*qb;        B[7]  = bt[1];
        B[8]  = 2.f*qb*qd - 2.f*qa*qc;        B[9]  = 2.f*qa*qb + 2.f*qc*qd;        B[10] = 1.f - 2.f*qb*qb - 2.f*qc*qc;  B[11] = bt[2];
        B[12] = 0.f; B[13] = 0.f; B[14] = 0.f; B[15] = 1.f;

        float ax = xyz[0], ay = xyz[1], az = xyz[2];
        float u  = rpy[0], v  = rpy[1], w  = rpy[2];
        float th = theta[0];
        float co = cosf(th), si = sinf(th), omc = 1.f - co;

        float R[16];
        R[0]  = u*u + (v*v + w*w)*co;   R[1]  = u*v*omc - w*si;          R[2]  = u*w*omc + v*si;
        R[3]  = (ax*(v*v + w*w) - u*(ay*v + az*w))*omc + (ay*w - az*v)*si;
        R[4]  = u*v*omc + w*si;         R[5]  = v*v + (u*u + w*w)*co;    R[6]  = v*w*omc - u*si;
        R[7]  = (ay*(u*u + w*w) - v*(ax*u + az*w))*omc + (az*u - ax*w)*si;
        R[8]  = u*w*omc - v*si;         R[9]  = v*w*omc + u*si;          R[10] = w*w + (u*u + v*v)*co;
        R[11] = (az*(u*u + v*v) - w*(ax*u + ay*v))*omc + (ax*v - ay*u)*si;
        R[12] = 0.f; R[13] = 0.f; R[14] = 0.f; R[15] = 1.f;

        float T[16];
        #pragma unroll
        for (int r = 0; r < 4; r++)
            #pragma unroll
            for (int c = 0; c < 4; c++) {
                float s = 0.f;
                #pragma unroll
                for (int k = 0; k < 4; k++) s += R[r*4 + k] * B[k*4 + c];
                T[r*4 + c] = s;
            }

        const float* X = (part == 0) ? B : T;
        #pragma unroll
        for (int i = 0; i < 12; i++) sxf[i] = X[i];

        if (dp == 0) {
            // out: [0]=all, [1]=base_obj, [2]=child_obj, [3..18]=base_T, [19..34]=rel_T
            #pragma unroll
            for (int i = 0; i < 16; i++) { out[3 + i] = B[i]; out[19 + i] = R[i]; }
        }
    }
    __syncthreads();

    const float t0 = sxf[0], t1 = sxf[1], t2  = sxf[2],  t3  = sxf[3];
    const float t4 = sxf[4], t5 = sxf[5], t6  = sxf[6],  t7  = sxf[7];
    const float t8 = sxf[8], t9 = sxf[9], t10 = sxf[10], t11 = sxf[11];

    const float* camP = cam + part * NPTS * 3;
    const float* cadP = cad + part * NPTS * 3;

    // pass 1: compute transformed points into g_tmp, track x range
    float mn = 1e30f, mx = -1e30f;
    for (int j = tid; j < NPTS; j += TPB_B) {
        float x, y, z;
        if (dir == 0) {
            x = camP[3*j]; y = camP[3*j + 1]; z = camP[3*j + 2];
        } else {
            float a = cadP[3*j], b = cadP[3*j + 1], c = cadP[3*j + 2];
            x = t0*a + t1*b + t2*c  + t3;
            y = t4*a + t5*b + t6*c  + t7;
            z = t8*a + t9*b + t10*c + t11;
        }
        g_tmp[dp][j] = make_float4(x, y, z, x*x + y*y + z*z);
        mn = fminf(mn, x); mx = fmaxf(mx, x);
    }
    sred[tid] = mn; __syncthreads();
    for (int s = TPB_B/2; s; s >>= 1) { if (tid < s) sred[tid] = fminf(sred[tid], sred[tid + s]); __syncthreads(); }
    if (tid == 0) s_xmin = sred[0];
    __syncthreads();
    sred[tid] = mx; __syncthreads();
    for (int s = TPB_B/2; s; s >>= 1) { if (tid < s) sred[tid] = fmaxf(sred[tid], sred[tid + s]); __syncthreads(); }
    if (tid == 0) {
        float range = sred[0] - s_xmin;
        s_inv = (range > 0.f) ? ((float)NBIN * (1.f - 1e-6f)) / range : 0.f;
        g_xmin[dp] = s_xmin; g_inv[dp] = s_inv;
    }
    for (int i = tid; i < NBIN; i += TPB_B) shist[i] = 0;
    __syncthreads();

    // pass 2: histogram
    const float xmin = s_xmin, inv = s_inv;
    for (int j = tid; j < NPTS; j += TPB_B)
        atomicAdd(&shist[bin_of(g_tmp[dp][j].x, xmin, inv)], 1);
    __syncthreads();

    // exclusive scan (serial, NBIN=256, negligible)
    if (tid == 0) {
        int acc = 0;
        for (int i = 0; i < NBIN; i++) { sstart[i] = acc; acc += shist[i]; }
        sstart[NBIN] = acc;   // = NPTS
    }
    __syncthreads();
    for (int i = tid; i < NBIN; i += TPB_B) soff[i] = sstart[i];
    for (int i = tid; i <= NBIN; i += TPB_B) g_bs[dp][i] = sstart[i];
    __syncthreads();

    // pass 3: scatter (within-bin order nondeterministic; min is order-free)
    for (int j = tid; j < NPTS; j += TPB_B) {
        float4 p = g_tmp[dp][j];
        int pos = atomicAdd(&soff[bin_of(p.x, xmin, inv)], 1);
        g_db[dp][pos] = p;
    }
}

// ---------------------------------------------------------------------------
// k_search: grid (QBLK, 4). One query per WARP (coalesced candidate loads).
// Queries of dp are exactly g_db[dp^1] (pre-sorted -> warp-coherent windows;
// order irrelevant since only the mean is needed).
// Exact NN: phase 1 rings outward from the query's bin until a candidate is
// found (upper bound best0); phase 2 scans the contiguous bin range covering
// [qx-sqrt(best0), qx+sqrt(best0)] -> exact min. Ticket tail -> fp64 means.
// ---------------------------------------------------------------------------
__global__ void __launch_bounds__(TPB_S)
k_search(const float* __restrict__ pw, float* __restrict__ out)
{
    __shared__ int    sbins[NBIN + 1];
    __shared__ double swsum[WPB];
    __shared__ double st[TPB_S];
    __shared__ int    s_last;

    const int dp   = blockIdx.y;
    const int tid  = threadIdx.x;
    const int lane = tid & 31;
    const int wid  = tid >> 5;

    for (int i = tid; i <= NBIN; i += TPB_S) sbins[i] = g_bs[dp][i];
    __syncthreads();

    const float4* __restrict__ db = g_db[dp];
    const float4* __restrict__ qa = g_db[dp ^ 1];
    const float xmin = g_xmin[dp], inv = g_inv[dp];

    double wsum = 0.0;
    const int wglobal = blockIdx.x * WPB + wid;   // 0..255 within dp

    for (int qi = 0; qi < QPW; qi++) {
        const int q = wglobal * QPW + qi;
        const float4 Q = qa[q];                   // broadcast load
        const float nqx = -2.f*Q.x, nqy = -2.f*Q.y, nqz = -2.f*Q.z, qn = Q.w;
        const int b0 = bin_of(Q.x, xmin, inv);

        // phase 1: ring out from b0 until a candidate found
        float m1 = scan_range(db, sbins[b0], sbins[b0 + 1], nqx, nqy, nqz, lane);
        m1 = warp_min(m1);
        for (int r = 1; m1 > 1e29f; r++) {
            const int l = b0 - r, rr = b0 + r;
            if (l >= 0)    m1 = fminf(m1, scan_range(db, sbins[l],  sbins[l + 1],  nqx, nqy, nqz, lane));
            if (rr < NBIN) m1 = fminf(m1, scan_range(db, sbins[rr], sbins[rr + 1], nqx, nqy, nqz, lane));
            m1 = warp_min(m1);
            if (l < 0 && rr >= NBIN) break;       // whole db scanned
        }

        // phase 2: certified window (any closer point has |dx| <= sqrt(best0))
        const float s = sqrtf(fmaxf(qn + m1, 0.f));
        const int lo = bin_of(Q.x - s, xmin, inv);
        const int hi = bin_of(Q.x + s, xmin, inv);
        float m2 = scan_range(db, sbins[lo], sbins[hi + 1], nqx, nqy, nqz, lane);
        m2 = warp_min(fminf(m1, m2));

        wsum += (double)sqrtf(fmaxf(qn + m2, 0.f));   // warp-uniform
    }

    if (lane == 0) swsum[wid] = wsum;
    __syncthreads();
    if (tid == 0) {
        double b = 0.0;
        #pragma unroll
        for (int i = 0; i < WPB; i++) b += swsum[i];   // deterministic order
        g_bsum[blockIdx.x + QBLK * dp] = b;
        __threadfence();
        unsigned int ticket = atomicAdd(&g_count, 1u);
        s_last = (ticket == NBLK_S - 1) ? 1 : 0;
    }
    __syncthreads();
    if (!s_last) return;

    __threadfence();
    st[tid] = (tid < NBLK_S) ? g_bsum[tid] : 0.0;
    __syncthreads();
    // part0 = entries [0..63] (dp 0,1), part1 = [64..127] (dp 2,3)
    for (int s = 32; s; s >>= 1) {
        if (tid < NBLK_S && (tid & 63) < s) st[tid] += st[tid + s];
        __syncthreads();
    }
    if (tid == 0) {
        double obj0 = st[0]  / (double)NPTS;
        double obj1 = st[64] / (double)NPTS;
        out[1] = (float)obj0;
        out[2] = (float)obj1;
        out[0] = (float)(((double)pw[0] * obj0 + (double)pw[1] * obj1) / 2.0);
        g_count = 0;   // reset for next graph replay
    }
}

// ---------------------------------------------------------------------------
extern "C" void kernel_launch(void* const* d_in, const int* in_sizes, int n_in,
                              void* d_out, int out_size)
{
    const float* cam  = (const float*)d_in[0];  // camera_pts [2,8192,3]
    const float* cad  = (const float*)d_in[1];  // cad_pts    [2,8192,3]
    const float* xyz  = (const float*)d_in[2];  // [1,3]
    const float* rpy  = (const float*)d_in[3];  // [1,3]
    const float* pw   = (const float*)d_in[4];  // [2]
    const float* quat = (const float*)d_in[5];  // [4]
    const float* bt   = (const float*)d_in[6];  // [3,1]
    const float* th   = (const float*)d_in[7];  // [1]
    float* out = (float*)d_out;

    k_build<<<4, TPB_B>>>(cam, cad, xyz, rpy, quat, bt, th, out);
    dim3 grid(QBLK, 4);
    k_search<<<grid, TPB_S>>>(pw, out);
}